// round 2
// baseline (speedup 1.0000x reference)
#include <cuda_runtime.h>
#include <math.h>

// Problem constants (from reference): N_OBJ=1024, C_DET=8, C_SEG=4, H=W=28
#define C_DET 8
#define C_SEG 4
#define HW 784           // 28*28
#define HW4 196          // HW / 4 (float4 units)
#define N_OBJ 1024
#define NB 8             // objects per block
#define NBLK_X (N_OBJ / NB)   // 128
#define RTHREADS 256

// Global accumulators (doubles: atomic-order invariant, so rel_err
// is dominated by float streaming sums only).
__device__ double g_A[C_DET][C_SEG];   // overlap matrix
__device__ double g_denom[C_DET];      // per-det-class mask sum

__global__ void zero_kernel() {
    int t = threadIdx.x;
    if (t < C_DET * C_SEG) ((double*)g_A)[t] = 0.0;
    if (t < C_DET) g_denom[t] = 0.0;
}

// Streaming reduction: block = (n-chunk, det class c).
// For each pixel-quad: 1 det float4 load + 4 seg float4 loads (one per seg class),
// accumulating denom and the 4 dot products.
__global__ __launch_bounds__(RTHREADS) void reduce_kernel(
    const float4* __restrict__ det4,   // (N,C_DET,HW4) float4
    const float4* __restrict__ seg4)   // (N,C_DET,C_SEG,HW4) float4
{
    const int c  = blockIdx.y;
    const int n0 = blockIdx.x * NB;

    float dsum = 0.0f;
    float a0 = 0.0f, a1 = 0.0f, a2 = 0.0f, a3 = 0.0f;

    for (int t = threadIdx.x; t < NB * HW4; t += RTHREADS) {
        const int nl = t / HW4;
        const int q  = t - nl * HW4;
        const long m = (long)(n0 + nl) * C_DET + c;

        const float4 d = det4[m * HW4 + q];
        dsum += (d.x + d.y) + (d.z + d.w);

        const long sb = m * (C_SEG * HW4) + q;
        float4 v;
        v = seg4[sb + 0 * HW4]; a0 += d.x * v.x + d.y * v.y + d.z * v.z + d.w * v.w;
        v = seg4[sb + 1 * HW4]; a1 += d.x * v.x + d.y * v.y + d.z * v.z + d.w * v.w;
        v = seg4[sb + 2 * HW4]; a2 += d.x * v.x + d.y * v.y + d.z * v.z + d.w * v.w;
        v = seg4[sb + 3 * HW4]; a3 += d.x * v.x + d.y * v.y + d.z * v.z + d.w * v.w;
    }

    // Warp reduce 5 scalars
    #pragma unroll
    for (int off = 16; off; off >>= 1) {
        dsum += __shfl_xor_sync(0xFFFFFFFFu, dsum, off);
        a0   += __shfl_xor_sync(0xFFFFFFFFu, a0, off);
        a1   += __shfl_xor_sync(0xFFFFFFFFu, a1, off);
        a2   += __shfl_xor_sync(0xFFFFFFFFu, a2, off);
        a3   += __shfl_xor_sync(0xFFFFFFFFu, a3, off);
    }

    __shared__ float sm[5][RTHREADS / 32];
    const int wid = threadIdx.x >> 5;
    const int lid = threadIdx.x & 31;
    if (lid == 0) {
        sm[0][wid] = dsum; sm[1][wid] = a0; sm[2][wid] = a1;
        sm[3][wid] = a2;   sm[4][wid] = a3;
    }
    __syncthreads();

    if (threadIdx.x == 0) {
        float r[5] = {0, 0, 0, 0, 0};
        #pragma unroll
        for (int w = 0; w < RTHREADS / 32; w++) {
            r[0] += sm[0][w]; r[1] += sm[1][w]; r[2] += sm[2][w];
            r[3] += sm[3][w]; r[4] += sm[4][w];
        }
        atomicAdd(&g_denom[c], (double)r[0]);
        atomicAdd(&g_A[c][0], (double)r[1]);
        atomicAdd(&g_A[c][1], (double)r[2]);
        atomicAdd(&g_A[c][2], (double)r[3]);
        atomicAdd(&g_A[c][3], (double)r[4]);
    }
}

// One block of 1024 threads: build edge weights w[8], compute per-object
// probs and BCE(target=1) = mean(-max(log p, -100)).
__global__ __launch_bounds__(N_OBJ) void finalize_kernel(
    const float* __restrict__ dcp,       // (N_OBJ, C_DET)
    const int* __restrict__ edge_i,      // int32 (JAX default int)
    const int* __restrict__ edge_j,
    int n_edges,
    float* __restrict__ out)
{
    __shared__ float w[C_DET];
    __shared__ float red[N_OBJ / 32];
    const int t = threadIdx.x;

    if (t < C_DET) w[t] = 0.0f;
    __syncthreads();

    if (t < n_edges && t < N_OBJ) {
        const int i = edge_i[t];
        const int j = edge_j[t];
        atomicAdd(&w[j], (float)(g_A[j][i] / g_denom[j]));
    }
    __syncthreads();

    float p = 0.0f;
    #pragma unroll
    for (int c = 0; c < C_DET; c++) p += dcp[t * C_DET + c] * w[c];
    float l = -fmaxf(logf(p), -100.0f);

    #pragma unroll
    for (int off = 16; off; off >>= 1) l += __shfl_xor_sync(0xFFFFFFFFu, l, off);
    if ((t & 31) == 0) red[t >> 5] = l;
    __syncthreads();

    if (t < 32) {
        float v = red[t];
        #pragma unroll
        for (int off = 16; off; off >>= 1) v += __shfl_xor_sync(0xFFFFFFFFu, v, off);
        if (t == 0) out[0] = v / (float)N_OBJ;
    }
}

extern "C" void kernel_launch(void* const* d_in, const int* in_sizes, int n_in,
                              void* d_out, int out_size) {
    // metadata order: det_class_probs (f32), det_mask_probs (f32),
    //                 seg_mask_probs (f32), edge_i (i32), edge_j (i32)
    const float*  dcp = (const float*)d_in[0];
    const float4* det = (const float4*)d_in[1];
    const float4* seg = (const float4*)d_in[2];
    const int*    ei  = (const int*)d_in[3];
    const int*    ej  = (const int*)d_in[4];
    const int n_edges = in_sizes[3];
    float* out = (float*)d_out;

    zero_kernel<<<1, 64>>>();
    reduce_kernel<<<dim3(NBLK_X, C_DET), RTHREADS>>>(det, seg);
    finalize_kernel<<<1, N_OBJ>>>(dcp, ei, ej, n_edges, out);
}